// round 14
// baseline (speedup 1.0000x reference)
#include <cuda_runtime.h>
#include <cstdint>

#define NG 768
#define H  128

// Prep outputs, [k][gene]-major.
__device__ float g_AiT[H * NG];  // (X@W1a^T + b1)^T
__device__ float g_YT [H * NG];  // (X@Wb)^T
__device__ float g_BjT[H * NG];  // (X@W1b^T)^T
__device__ float g_XT [H * NG];  // X^T

__device__ __forceinline__ float tf32f(float v) {
    uint32_t r; asm("cvt.rna.tf32.f32 %0, %1;" : "=r"(r) : "f"(v));
    return __uint_as_float(r);
}
__device__ __forceinline__ void mma_tf32(float* d, const uint32_t* a, const uint32_t* b) {
    asm volatile("mma.sync.aligned.m16n8k8.row.col.f32.tf32.tf32.f32 "
        "{%0,%1,%2,%3}, {%4,%5,%6,%7}, {%8,%9}, {%0,%1,%2,%3};"
        : "+f"(d[0]), "+f"(d[1]), "+f"(d[2]), "+f"(d[3])
        : "r"(a[0]), "r"(a[1]), "r"(a[2]), "r"(a[3]), "r"(b[0]), "r"(b[1]));
}

// ---------------- prep (unchanged, validated) ----------------------------
__global__ __launch_bounds__(256)
void prep_gemm(const float* __restrict__ X, const float* __restrict__ W1,
               const float* __restrict__ b1, const float* __restrict__ Wb) {
    extern __shared__ float psm[];
    float* Ws = psm;               // [128][132], Ws[t][k]
    float* Xs = psm + 128 * 132;   // [16][132],  Xs[g][k]

    int tid = threadIdx.x;
    int m = blockIdx.y;
    int g0 = blockIdx.x * 16;

    if (m < 2) {
        const float4* W14 = (const float4*)W1;   // W1 [128][256]
        #pragma unroll
        for (int it = 0; it < 16; ++it) {
            int idx = tid + 256 * it;
            int t = idx >> 5, kc = idx & 31;
            *(float4*)&Ws[t * 132 + kc * 4] = W14[t * 64 + m * 32 + kc];
        }
    } else {
        #pragma unroll 8
        for (int it = 0; it < 64; ++it) {        // Ws[t][k] = Wb[k][t]
            int idx = tid + 256 * it;
            int k = idx >> 7, t = idx & 127;
            Ws[t * 132 + k] = Wb[k * H + t];
        }
    }
    {
        const float4* X4 = (const float4*)X;
        #pragma unroll
        for (int it = 0; it < 2; ++it) {
            int idx = tid + 256 * it;
            int g = idx >> 5, kc = idx & 31;
            *(float4*)&Xs[g * 132 + kc * 4] = X4[(g0 + g) * 32 + kc];
        }
    }
    __syncthreads();

    int g  = tid & 15;
    int tg = tid >> 4;
    int t0 = tg * 8;

    float acc[8];
    #pragma unroll
    for (int i = 0; i < 8; ++i) acc[i] = 0.f;

    #pragma unroll 4
    for (int k4 = 0; k4 < 32; ++k4) {
        float4 x = *(const float4*)&Xs[g * 132 + k4 * 4];
        #pragma unroll
        for (int i = 0; i < 8; ++i) {
            float4 w = *(const float4*)&Ws[(t0 + i) * 132 + k4 * 4];
            acc[i] = fmaf(x.x, w.x, fmaf(x.y, w.y, fmaf(x.z, w.z, fmaf(x.w, w.w, acc[i]))));
        }
    }

    int gene = g0 + g;
    #pragma unroll
    for (int i = 0; i < 8; ++i) {
        int t = t0 + i;
        float v = acc[i];
        if (m == 0) {
            g_AiT[t * NG + gene] = v + __ldg(&b1[t]);
        } else if (m == 1) {
            g_BjT[t * NG + gene] = v;
        } else {
            g_YT[t * NG + gene] = v;
        }
    }

    if (m == 1) {
        #pragma unroll
        for (int it = 0; it < 8; ++it) {
            int idx = tid + 256 * it;
            int k = idx >> 4, gg = idx & 15;
            g_XT[k * NG + g0 + gg] = Xs[gg * 132 + k];
        }
    }
}

#define YPS 130   // float2 row stride for Yp/Xp (128 k + 2 pad)

// ---- pair kernel: short all-warp mma phase, then all-warp MLP loop ------
__global__ __launch_bounds__(512, 1)
void pair_kernel(const float* __restrict__ W2, const float* __restrict__ b2,
                 const float* __restrict__ bb, float* __restrict__ out) {
    extern __shared__ float sm[];
    float*  As    = sm;                  // [128][64] k-major Ai'
    float*  Bs    = As + 128 * 64;       // [128][64] k-major Bj
    float*  wd    = Bs + 128 * 64;       // [128][2] = (wd0, wd1)
    float*  sPart = wd + 128 * 2;        // [2 side][4 kq][2][64] partials
    float*  aff   = sPart + 1024;        // [64][68] bilinear affinity
    float2* Yp    = (float2*)(aff + 64 * 68);  // [64][YPS] {tf32hi, tf32lo} per k
    float2* Xp    = Yp + 64 * YPS;

    int tid  = threadIdx.x;
    int w    = tid >> 5;
    int lane = tid & 31;
    int bi = blockIdx.y, bj = blockIdx.x;
    int bi64 = bi * 64, bj64 = bj * 64;

    const float4* A4g = (const float4*)g_AiT;  // row = 192 float4
    const float4* B4g = (const float4*)g_BjT;
    float4* As4 = (float4*)As;
    float4* Bs4 = (float4*)Bs;

    #pragma unroll
    for (int it = 0; it < 4; ++it) {            // 2048 float4 each
        int idx = tid + 512 * it;
        int k = idx >> 4, c = idx & 15;
        As4[idx] = A4g[k * 192 + bi * 16 + c];
        Bs4[idx] = B4g[k * 192 + bj * 16 + c];
    }
    if (tid < H) {
        float w0 = W2[tid], w1 = W2[H + tid], w2v = W2[2 * H + tid];
        ((float2*)wd)[tid] = make_float2(w0 - w1, w0 - w2v);
    }
    // Convert phase: gmem -> {tf32hi, tf32lo} float2, gene-major stride YPS.
    #pragma unroll
    for (int it = 0; it < 16; ++it) {
        int idx = tid + 512 * it;
        int g = idx & 63, k = idx >> 6;          // k = 0..127
        float yv = g_YT[k * NG + bi64 + g];
        float yh = tf32f(yv);
        Yp[g * YPS + k] = make_float2(yh, tf32f(yv - yh));
        float xv = g_XT[k * NG + bj64 + g];
        float xh = tf32f(xv);
        Xp[g * YPS + k] = make_float2(xh, tf32f(xv - xh));
    }
    __syncthreads();

    // Phase 1a: factorized linear sums (all warps, k-quarter split).
    {
        int e    = tid & 63;
        int kq   = (tid >> 6) & 3;
        int side = tid >> 8;
        const float* src = side ? Bs : As;
        float s0 = 0.f, s1 = 0.f;
        #pragma unroll 4
        for (int k = 0; k < 32; ++k) {
            int kk = kq * 32 + k;
            float  v = src[kk * 64 + e];
            float2 ww = ((const float2*)wd)[kk];
            s0 = fmaf(v, ww.x, s0);
            s1 = fmaf(v, ww.y, s1);
        }
        sPart[side * 512 + kq * 128 + e]      = s0;
        sPart[side * 512 + kq * 128 + 64 + e] = s1;
    }

    // Phase 1b: affinity mma, ALL 16 warps, each one m16n16 tile (3xTF32).
    {
        int gid  = lane >> 2;      // 0..7
        int tig  = lane & 3;       // 0..3
        int mOff = (w & 3) * 16;
        int nOff = (w >> 2) * 16;
        int r0 = mOff + gid, r1 = mOff + gid + 8;
        float d0[4] = {0.f, 0.f, 0.f, 0.f};
        float d1[4] = {0.f, 0.f, 0.f, 0.f};
        #pragma unroll 4
        for (int ks = 0; ks < 16; ++ks) {
            int k0 = ks * 8 + tig;
            float2 aA = Yp[r0 * YPS + k0];
            float2 aB = Yp[r1 * YPS + k0];
            float2 aC = Yp[r0 * YPS + k0 + 4];
            float2 aD = Yp[r1 * YPS + k0 + 4];
            uint32_t ah[4] = {__float_as_uint(aA.x), __float_as_uint(aB.x),
                              __float_as_uint(aC.x), __float_as_uint(aD.x)};
            uint32_t al[4] = {__float_as_uint(aA.y), __float_as_uint(aB.y),
                              __float_as_uint(aC.y), __float_as_uint(aD.y)};
            float2 b0a = Xp[(nOff + gid) * YPS + k0];
            float2 b0b = Xp[(nOff + gid) * YPS + k0 + 4];
            uint32_t bh[2] = {__float_as_uint(b0a.x), __float_as_uint(b0b.x)};
            uint32_t bl[2] = {__float_as_uint(b0a.y), __float_as_uint(b0b.y)};
            mma_tf32(d0, ah, bh);
            mma_tf32(d0, ah, bl);
            mma_tf32(d0, al, bh);
            float2 b1a = Xp[(nOff + 8 + gid) * YPS + k0];
            float2 b1b = Xp[(nOff + 8 + gid) * YPS + k0 + 4];
            uint32_t ch[2] = {__float_as_uint(b1a.x), __float_as_uint(b1b.x)};
            uint32_t cl[2] = {__float_as_uint(b1a.y), __float_as_uint(b1b.y)};
            mma_tf32(d1, ah, ch);
            mma_tf32(d1, ah, cl);
            mma_tf32(d1, al, ch);
        }
        aff[r0 * 68 + nOff + 2 * tig]         = d0[0];
        aff[r0 * 68 + nOff + 2 * tig + 1]     = d0[1];
        aff[r1 * 68 + nOff + 2 * tig]         = d0[2];
        aff[r1 * 68 + nOff + 2 * tig + 1]     = d0[3];
        aff[r0 * 68 + nOff + 8 + 2 * tig]     = d1[0];
        aff[r0 * 68 + nOff + 8 + 2 * tig + 1] = d1[1];
        aff[r1 * 68 + nOff + 8 + 2 * tig]     = d1[2];
        aff[r1 * 68 + nOff + 8 + 2 * tig + 1] = d1[3];
    }
    __syncthreads();

    // Phase 2: MLP loop on ALL warps, 2i x 4j per thread.
    int tx = tid & 15;     // j group: j0 = tx*4
    int ty = tid >> 4;     // 0..31: i pair = ty*2, ty*2+1
    int j0 = tx * 4;

    const float2* AsF2 = (const float2*)As;   // row = 32 float2
    const float2* WdF2 = (const float2*)wd;

    float a01[8], a02[8];
    #pragma unroll
    for (int r = 0; r < 8; ++r) { a01[r] = 0.f; a02[r] = 0.f; }

    #pragma unroll 4
    for (int k = 0; k < H; ++k) {
        float2 a = AsF2[k * 32 + ty];
        float4 b = Bs4[k * 16 + tx];
        float2 ww = WdF2[k];
        float av[2] = {a.x, a.y};
        float bv[4] = {b.x, b.y, b.z, b.w};
        #pragma unroll
        for (int p = 0; p < 2; ++p) {
            #pragma unroll
            for (int q = 0; q < 4; ++q) {
                int r = p * 4 + q;
                float t = fabsf(av[p] + bv[q]);   // abs = FFMA srcmod
                a01[r] = fmaf(t, ww.x, a01[r]);
                a02[r] = fmaf(t, ww.y, a02[r]);
            }
        }
    }

    float db01 = b2[0] - b2[1];
    float db02 = b2[0] - b2[2];
    float bbv  = bb[0];

    float sB0v[4], sB1v[4];
    #pragma unroll
    for (int q = 0; q < 4; ++q) {
        int lj = j0 + q;
        sB0v[q] = (sPart[512 + lj]        + sPart[512 + 128 + lj])
                + (sPart[512 + 256 + lj]  + sPart[512 + 384 + lj]);
        sB1v[q] = (sPart[512 + 64 + lj]   + sPart[512 + 192 + lj])
                + (sPart[512 + 320 + lj]  + sPart[512 + 448 + lj]);
    }

    #pragma unroll
    for (int p = 0; p < 2; ++p) {
        int li = ty * 2 + p;
        int gi = bi64 + li;
        float sA0v = (sPart[li]        + sPart[128 + li])
                   + (sPart[256 + li]  + sPart[384 + li]);
        float sA1v = (sPart[64 + li]   + sPart[192 + li])
                   + (sPart[320 + li]  + sPart[448 + li]);
        float4 afq = *(const float4*)&aff[li * 68 + j0];
        float afv[4] = {afq.x, afq.y, afq.z, afq.w};
        float ov[4];
        #pragma unroll
        for (int q = 0; q < 4; ++q) {
            int r = p * 4 + q;
            float d01 = fmaf(0.5f, sA0v + sB0v[q] + a01[r], db01);  // l0-l1
            float d02 = fmaf(0.5f, sA1v + sB1v[q] + a02[r], db02);  // l0-l2
            float af  = afv[q] + bbv;
            // argmax first-occurrence: cls0 <=> d01>=0 && d02>=0;
            // cls2 <=> d02<0 && d02<d01
            float s = (d01 >= 0.f && d02 >= 0.f) ? 1.f
                    : ((d02 < 0.f && d02 < d01) ? -1.f : 0.f);
            int gj = bj64 + j0 + q;
            ov[q] = (gi == gj) ? 0.f : s * af;
        }
        float4 o; o.x = ov[0]; o.y = ov[1]; o.z = ov[2]; o.w = ov[3];
        *(float4*)&out[gi * NG + j0 + bj64] = o;
    }
}

extern "C" void kernel_launch(void* const* d_in, const int* in_sizes, int n_in,
                              void* d_out, int out_size) {
    const float* X  = (const float*)d_in[0];
    const float* W1 = (const float*)d_in[1];
    const float* b1 = (const float*)d_in[2];
    const float* W2 = (const float*)d_in[3];
    const float* b2 = (const float*)d_in[4];
    const float* Wb = (const float*)d_in[5];
    const float* bb = (const float*)d_in[6];
    float* out = (float*)d_out;

    size_t psmem = (size_t)(128 * 132 + 16 * 132) * sizeof(float);
    cudaFuncSetAttribute(prep_gemm, cudaFuncAttributeMaxDynamicSharedMemorySize,
                         (int)psmem);
    size_t smem = (size_t)(2 * 128 * 64 + 128 * 2 + 1024 + 64 * 68) * sizeof(float)
                + (size_t)(2 * 64 * YPS) * sizeof(float2);
    cudaFuncSetAttribute(pair_kernel, cudaFuncAttributeMaxDynamicSharedMemorySize,
                         (int)smem);

    prep_gemm<<<dim3(48, 3), 256, psmem>>>(X, W1, b1, Wb);
    pair_kernel<<<dim3(12, 12), 512, smem>>>(W2, b2, bb, out);
}